// round 10
// baseline (speedup 1.0000x reference)
#include <cuda_runtime.h>
#include <cuda_fp16.h>

#define NMAX 50000
#define EMAX 800000
#define E2MAX (EMAX + NMAX)
#define HC 160
#define HCP 192   // padded h1 row: 384 B, 128B-aligned
#define NH 5
#define NC 32
#define WPB 8

// ---- scratch (static device globals) ----
__device__ __align__(128) __half g_h1h[(size_t)NMAX * HCP];
__device__ __align__(16) float g_as1[NMAX * 8];     // as1 fp32, padded to 8
__device__ float g_ad1[NMAX * NH];
__device__ __align__(16) __half g_h2h[NMAX * 8];    // h2 (fp16), 16B/node
__device__ float g_ad2[NMAX * NH];
__device__ float g_ce1[NH], g_ce2[NH];
__device__ float g_easum;
__device__ int   g_cnt[NMAX];
__device__ int   g_rowptr[NMAX + 1];
__device__ int   g_pos[E2MAX];
__device__ __align__(8) int2 g_edge[E2MAX];         // {src, ea-bits}

// ---- combo: [count in-degree (save pos) + easum] || [node1 transform] ----
__global__ void k_combo(const int* __restrict__ dst, const float* __restrict__ ea,
                        const float* __restrict__ x, const float* __restrict__ W1,
                        const float* __restrict__ asrc, const float* __restrict__ adst,
                        int E, int N, int countBlocks) {
    if ((int)blockIdx.x < countBlocks) {
        int e = blockIdx.x * blockDim.x + threadIdx.x;
        int E2 = E + N;
        float s = 0.f;
        if (e < E2) {
            int d = (e < E) ? __ldg(&dst[e]) : (e - E);
            g_pos[e] = atomicAdd(&g_cnt[d], 1);
            if (e < E) s = __ldg(&ea[e]);
        }
        #pragma unroll
        for (int o = 16; o; o >>= 1) s += __shfl_xor_sync(~0u, s, o);
        if ((threadIdx.x & 31) == 0 && s != 0.f) atomicAdd(&g_easum, s);
    } else {
        int warp = (((int)blockIdx.x - countBlocks) * blockDim.x + threadIdx.x) >> 5;
        int lane = threadIdx.x & 31;
        if (warp >= N) return;
        int n = warp;
        float xf[5];
        #pragma unroll
        for (int f = 0; f < 5; f++) xf[f] = __ldg(&x[n * 5 + f]);
        #pragma unroll
        for (int h = 0; h < NH; h++) {
            int col = h * NC + lane;
            float acc = 0.f;
            #pragma unroll
            for (int f = 0; f < 5; f++) acc = fmaf(xf[f], __ldg(&W1[f * HC + col]), acc);
            g_h1h[(size_t)n * HCP + col] = __float2half(acc);
            float ps = acc * __ldg(&asrc[col]);
            float pd = acc * __ldg(&adst[col]);
            #pragma unroll
            for (int o = 16; o; o >>= 1) {
                ps += __shfl_xor_sync(~0u, ps, o);
                pd += __shfl_xor_sync(~0u, pd, o);
            }
            if (lane == 0) { g_as1[n * 8 + h] = ps; g_ad1[n * NH + h] = pd; }
        }
    }
}

// ---- single-block exclusive scan + attn constants ----
__global__ void k_scan(const float* __restrict__ We1, const float* __restrict__ ae1,
                       const float* __restrict__ We2, const float* __restrict__ ae2,
                       int N, int E2) {
    __shared__ int wsum[32];
    int t = threadIdx.x;
    int lane = t & 31, w = t >> 5;
    if (t < NH) {
        float s = 0.f;
        for (int c = 0; c < NC; c++) s += We1[t * NC + c] * ae1[t * NC + c];
        g_ce1[t] = s;
        g_ce2[t] = We2[t] * ae2[t];
    }
    int chunk = (N + 1023) / 1024;
    int b = t * chunk, e = min(b + chunk, N);
    int s = 0;
    for (int i = b; i < e; i++) s += g_cnt[i];
    int inc = s;
    #pragma unroll
    for (int o = 1; o < 32; o <<= 1) {
        int v = __shfl_up_sync(~0u, inc, o);
        if (lane >= o) inc += v;
    }
    if (lane == 31) wsum[w] = inc;
    __syncthreads();
    if (w == 0) {
        int v = wsum[lane];
        int iv = v;
        #pragma unroll
        for (int o = 1; o < 32; o <<= 1) {
            int u = __shfl_up_sync(~0u, iv, o);
            if (lane >= o) iv += u;
        }
        wsum[lane] = iv - v;
    }
    __syncthreads();
    int run = wsum[w] + inc - s;
    for (int i = b; i < e; i++) {
        g_rowptr[i] = run;
        run += g_cnt[i];
    }
    if (t == 0) g_rowptr[N] = E2;
}

// ---- scatter edges into CSR: atomic-free ----
__global__ void k_scatter(const int* __restrict__ src, const int* __restrict__ dst,
                          const float* __restrict__ ea, int E, int N, float invE) {
    int e = blockIdx.x * blockDim.x + threadIdx.x;
    int E2 = E + N;
    if (e >= E2) return;
    int s, d; float av;
    if (e < E) { s = __ldg(&src[e]); d = __ldg(&dst[e]); av = __ldg(&ea[e]); }
    else       { s = d = e - E; av = g_easum * invE; }
    int2 rec; rec.x = s; rec.y = __float_as_int(av);
    g_edge[__ldg(&g_rowptr[d]) + g_pos[e]] = rec;
}

// ---- FUSED1: layer1 softmax+agg + relu + layer2 transform ----
__global__ void __launch_bounds__(256, 5)
k_fused1(const float* __restrict__ b1, const float* __restrict__ W2,
         const float* __restrict__ as2w, const float* __restrict__ ad2w,
         int N) {
    __shared__ __align__(16) float s_rec[WPB][32][8];
    int warp = (blockIdx.x * blockDim.x + threadIdx.x) >> 5;
    int lane = threadIdx.x & 31;
    int w = (threadIdx.x >> 5);
    if (warp >= N) return;
    int n = warp;
    int row = g_rowptr[n], end = g_rowptr[n + 1];

    float adh[NH], ceh[NH];
    #pragma unroll
    for (int h = 0; h < NH; h++) {
        adh[h] = __ldg(&g_ad1[n * NH + h]);
        ceh[h] = g_ce1[h];
    }
    int hA = lane >> 4;

    float ax0 = 0.f, ay0 = 0.f, ax1 = 0.f, ay1 = 0.f, ax2 = 0.f, ay2 = 0.f;
    float denh[NH] = {0.f, 0.f, 0.f, 0.f, 0.f};

    for (int base = row; base < end; base += 32) {
        int cnt = min(32, end - base);
        if (lane < cnt) {
            int2 r = g_edge[base + lane];
            int sA = r.x;
            float av = __int_as_float(r.y);
            float4 a4 = __ldg((const float4*)(g_as1 + sA * 8));
            float a5 = __ldg(&g_as1[sA * 8 + 4]);
            float lv[NH] = {a4.x, a4.y, a4.z, a4.w, a5};
            float ex[NH];
            #pragma unroll
            for (int h = 0; h < NH; h++) {
                float l = lv[h] + adh[h] + av * ceh[h];
                l = l > 0.f ? l : 0.2f * l;
                ex[h] = __expf(l);
                denh[h] += ex[h];
            }
            float2* rec = (float2*)s_rec[w][lane];
            float2 p0; p0.x = ex[0]; p0.y = ex[2];
            float2 p1; p1.x = ex[1]; p1.y = ex[3];
            float2 p2; p2.x = ex[4]; p2.y = __int_as_float(sA);
            rec[0] = p0; rec[1] = p1; rec[2] = p2;
        }
        __syncwarp();
        #pragma unroll 2
        for (int j = 0; j < cnt; j++) {
            float2 pab = *(const float2*)&s_rec[w][j][2 * hA];
            float2 p4s = *(const float2*)&s_rec[w][j][4];
            int s = __float_as_int(p4s.y);
            float a0 = pab.x, a1 = pab.y, a2 = p4s.x;
            const __half2* hb = (const __half2*)(g_h1h + (size_t)s * HCP);
            __half2 v0 = __ldg(&hb[lane]);
            __half2 v1 = __ldg(&hb[32 + lane]);
            float2 f0 = __half22float2(v0), f1 = __half22float2(v1);
            ax0 = fmaf(a0, f0.x, ax0); ay0 = fmaf(a0, f0.y, ay0);
            ax1 = fmaf(a1, f1.x, ax1); ay1 = fmaf(a1, f1.y, ay1);
            if (lane < 16) {
                __half2 v2 = __ldg(&hb[64 + lane]);
                float2 f2 = __half22float2(v2);
                ax2 = fmaf(a2, f2.x, ax2); ay2 = fmaf(a2, f2.y, ay2);
            }
        }
        __syncwarp();
    }

    #pragma unroll
    for (int h = 0; h < NH; h++) {
        #pragma unroll
        for (int o = 16; o; o >>= 1) denh[h] += __shfl_xor_sync(~0u, denh[h], o);
        denh[h] += 1e-16f;
    }
    float dA = denh[hA], dB = denh[2 + hA], dC = denh[4];

    float a2h[NH] = {0.f, 0.f, 0.f, 0.f, 0.f};
    int k; float v;
    #define DO_CH(val, dd, kk) \
        k = (kk); v = (val) / (dd) + __ldg(&b1[k]); v = fmaxf(v, 0.f); \
        _Pragma("unroll") \
        for (int h = 0; h < NH; h++) a2h[h] = fmaf(v, __ldg(&W2[k * NH + h]), a2h[h]);
    DO_CH(ax0, dA, 2 * lane)
    DO_CH(ay0, dA, 2 * lane + 1)
    DO_CH(ax1, dB, 64 + 2 * lane)
    DO_CH(ay1, dB, 65 + 2 * lane)
    if (lane < 16) {
        DO_CH(ax2, dC, 128 + 2 * lane)
        DO_CH(ay2, dC, 129 + 2 * lane)
    }
    #undef DO_CH
    #pragma unroll
    for (int h = 0; h < NH; h++)
        #pragma unroll
        for (int o = 16; o; o >>= 1) a2h[h] += __shfl_xor_sync(~0u, a2h[h], o);
    if (lane == 0) {
        // h2 packed as 8 halves (one 16B record)
        __half2 q0 = __floats2half2_rn(a2h[0], a2h[1]);
        __half2 q1 = __floats2half2_rn(a2h[2], a2h[3]);
        __half2 q2 = __floats2half2_rn(a2h[4], 0.f);
        __half2 q3 = __floats2half2_rn(0.f, 0.f);
        int4 pk;
        pk.x = *(int*)&q0; pk.y = *(int*)&q1; pk.z = *(int*)&q2; pk.w = *(int*)&q3;
        *(int4*)(g_h2h + n * 8) = pk;
        #pragma unroll
        for (int h = 0; h < NH; h++)
            g_ad2[n * NH + h] = a2h[h] * __ldg(&ad2w[h]);
    }
}

// ---- FUSED2: layer2 softmax+agg + head-mean + Wlin + sigmoid ----
// per-edge scattered traffic: ONE 16B load (h2 fp16); as2 derived in-flight.
__global__ void k_fused2(const float* __restrict__ as2w,
                         const float* __restrict__ b2, const float* __restrict__ Wlin,
                         float* __restrict__ out, int N) {
    int warp = (blockIdx.x * blockDim.x + threadIdx.x) >> 5;
    int lane = threadIdx.x & 31;
    if (warp >= N) return;
    int n = warp;
    int row = g_rowptr[n], end = g_rowptr[n + 1];

    float adh[NH], ceh[NH], aw[NH];
    #pragma unroll
    for (int h = 0; h < NH; h++) {
        adh[h] = __ldg(&g_ad2[n * NH + h]);
        ceh[h] = g_ce2[h];
        aw[h]  = __ldg(&as2w[h]);
    }
    float acch[NH] = {0.f, 0.f, 0.f, 0.f, 0.f};
    float denh[NH] = {0.f, 0.f, 0.f, 0.f, 0.f};

    for (int base = row; base < end; base += 32) {
        int e = base + lane;
        if (e < end) {
            int2 r = g_edge[e];
            int s = r.x;
            float av = __int_as_float(r.y);
            int4 vp = __ldg((const int4*)(g_h2h + s * 8));
            float2 f01 = __half22float2(*(__half2*)&vp.x);
            float2 f23 = __half22float2(*(__half2*)&vp.y);
            float2 f45 = __half22float2(*(__half2*)&vp.z);
            float h2v[NH] = {f01.x, f01.y, f23.x, f23.y, f45.x};
            #pragma unroll
            for (int h = 0; h < NH; h++) {
                float l = fmaf(h2v[h], aw[h], adh[h] + av * ceh[h]);
                l = l > 0.f ? l : 0.2f * l;
                float ex = __expf(l);
                denh[h] += ex;
                acch[h] = fmaf(ex, h2v[h], acch[h]);
            }
        }
    }
    #pragma unroll
    for (int h = 0; h < NH; h++)
        #pragma unroll
        for (int o = 16; o; o >>= 1) {
            acch[h] += __shfl_xor_sync(~0u, acch[h], o);
            denh[h] += __shfl_xor_sync(~0u, denh[h], o);
        }
    if (lane == 0) {
        float ssum = 0.f;
        #pragma unroll
        for (int h = 0; h < NH; h++) ssum += acch[h] / (denh[h] + 1e-16f);
        float y = (ssum * (1.0f / NH) + __ldg(&b2[0])) * __ldg(&Wlin[0]);
        out[n] = 1.0f / (1.0f + expf(-y));
    }
}

extern "C" void kernel_launch(void* const* d_in, const int* in_sizes, int n_in,
                              void* d_out, int out_size) {
    const float* x      = (const float*)d_in[0];
    const float* ea     = (const float*)d_in[1];
    const int*   src    = (const int*)d_in[2];
    const int*   dst    = (const int*)d_in[3];
    const float* W1     = (const float*)d_in[4];
    const float* a_src1 = (const float*)d_in[5];
    const float* a_dst1 = (const float*)d_in[6];
    const float* We1    = (const float*)d_in[7];
    const float* ae1    = (const float*)d_in[8];
    const float* b1     = (const float*)d_in[9];
    const float* W2     = (const float*)d_in[10];
    const float* a_src2 = (const float*)d_in[11];
    const float* a_dst2 = (const float*)d_in[12];
    const float* We2    = (const float*)d_in[13];
    const float* ae2    = (const float*)d_in[14];
    const float* b2     = (const float*)d_in[15];
    const float* Wlin   = (const float*)d_in[16];

    int N  = in_sizes[0] / 5;
    int E  = in_sizes[2];
    int E2 = E + N;
    float invE = 1.0f / (float)E;

    void* cntp = nullptr; void* easp = nullptr;
    cudaGetSymbolAddress(&cntp, g_cnt);
    cudaGetSymbolAddress(&easp, g_easum);
    cudaMemsetAsync(cntp, 0, N * sizeof(int));
    cudaMemsetAsync(easp, 0, sizeof(float));

    int countBlocks = (E2 + 255) / 256;
    int nodeBlocks  = (N * 32 + 255) / 256;
    k_combo<<<countBlocks + nodeBlocks, 256>>>(dst, ea, x, W1, a_src1, a_dst1, E, N, countBlocks);
    k_scan<<<1, 1024>>>(We1, ae1, We2, ae2, N, E2);
    k_scatter<<<(E2 + 255) / 256, 256>>>(src, dst, ea, E, N, invE);
    k_fused1<<<(N * 32 + 255) / 256, 256>>>(b1, W2, a_src2, a_dst2, N);
    k_fused2<<<(N * 32 + 255) / 256, 256>>>(a_src2, b2, Wlin, (float*)d_out, N);
}

// round 11
// speedup vs baseline: 1.0727x; 1.0727x over previous
#include <cuda_runtime.h>
#include <cuda_fp16.h>

#define NMAX 50000
#define EMAX 800000
#define E2MAX (EMAX + NMAX)
#define HC 160
#define HCP 192   // padded h1 row: 384 B, 128B-aligned
#define NH 5
#define NC 32
#define WPB 8

// ---- scratch (static device globals) ----
__device__ __align__(128) __half g_h1h[(size_t)NMAX * HCP];
__device__ __align__(16) float g_as1[NMAX * 8];     // as1 fp32, padded to 8
__device__ float g_ad1[NMAX * NH];
__device__ __align__(16) __half g_h2h[NMAX * 8];    // h2 (fp16), 16B/node
__device__ float g_ad2[NMAX * NH];
__device__ float g_ce1[NH], g_ce2[NH];
__device__ float g_wasad[5 * 16];                   // [f][j]: j<5 = w_as head j, j>=5 = w_ad head j-5
__device__ float g_easum;
__device__ int   g_cnt[NMAX];
__device__ int   g_rowptr[NMAX + 1];
__device__ int   g_pos[E2MAX];
__device__ __align__(8) int2 g_edge[E2MAX];         // {src, ea-bits}

// ---- pre: zero counters + attention constant tables ----
__global__ void k_pre(const float* __restrict__ We1, const float* __restrict__ ae1,
                      const float* __restrict__ We2, const float* __restrict__ ae2,
                      const float* __restrict__ W1,
                      const float* __restrict__ a_src1, const float* __restrict__ a_dst1,
                      int N) {
    int i = blockIdx.x * blockDim.x + threadIdx.x;
    if (i < N) g_cnt[i] = 0;
    if (blockIdx.x == 0) {
        int t = threadIdx.x;
        if (t == 0) g_easum = 0.f;
        if (t < NH) {
            float s = 0.f;
            for (int c = 0; c < NC; c++) s += We1[t * NC + c] * ae1[t * NC + c];
            g_ce1[t] = s;
            g_ce2[t] = We2[t] * ae2[t];
        }
        // w_asad: 50 entries
        if (t >= 64 && t < 114) {
            int u = t - 64;
            int f = u / 10, j = u % 10;
            int h = (j < 5) ? j : j - 5;
            const float* a = (j < 5) ? a_src1 : a_dst1;
            float s = 0.f;
            for (int c = 0; c < NC; c++) s += W1[f * HC + h * NC + c] * a[h * NC + c];
            g_wasad[f * 16 + j] = s;
        }
    }
}

// ---- combo: [count in-degree (save pos) + easum] || [node1 transform] ----
__global__ void k_combo(const int* __restrict__ dst, const float* __restrict__ ea,
                        const float* __restrict__ x, const float* __restrict__ W1,
                        int E, int N, int countBlocks) {
    if ((int)blockIdx.x < countBlocks) {
        int e = blockIdx.x * blockDim.x + threadIdx.x;
        int E2 = E + N;
        float s = 0.f;
        if (e < E2) {
            int d = (e < E) ? __ldg(&dst[e]) : (e - E);
            g_pos[e] = atomicAdd(&g_cnt[d], 1);
            if (e < E) s = __ldg(&ea[e]);
        }
        #pragma unroll
        for (int o = 16; o; o >>= 1) s += __shfl_xor_sync(~0u, s, o);
        if ((threadIdx.x & 31) == 0 && s != 0.f) atomicAdd(&g_easum, s);
    } else {
        int warp = (((int)blockIdx.x - countBlocks) * blockDim.x + threadIdx.x) >> 5;
        int lane = threadIdx.x & 31;
        if (warp >= N) return;
        int n = warp;
        float xf[5];
        #pragma unroll
        for (int f = 0; f < 5; f++) xf[f] = __ldg(&x[n * 5 + f]);
        // h1 = x@W1 (fp16 out), no reductions
        #pragma unroll
        for (int h = 0; h < NH; h++) {
            int col = h * NC + lane;
            float acc = 0.f;
            #pragma unroll
            for (int f = 0; f < 5; f++) acc = fmaf(xf[f], __ldg(&W1[f * HC + col]), acc);
            g_h1h[(size_t)n * HCP + col] = __float2half(acc);
        }
        // as1/ad1 via precomputed w_asad: lanes 0..9, no shuffles
        if (lane < 10) {
            float acc = 0.f;
            #pragma unroll
            for (int f = 0; f < 5; f++) acc = fmaf(xf[f], g_wasad[f * 16 + lane], acc);
            if (lane < 5) g_as1[n * 8 + lane] = acc;
            else          g_ad1[n * NH + (lane - 5)] = acc;
        }
    }
}

// ---- single-block exclusive scan ----
__global__ void k_scan(int N, int E2) {
    __shared__ int wsum[32];
    int t = threadIdx.x;
    int lane = t & 31, w = t >> 5;
    int chunk = (N + 1023) / 1024;
    int b = t * chunk, e = min(b + chunk, N);
    int s = 0;
    for (int i = b; i < e; i++) s += g_cnt[i];
    int inc = s;
    #pragma unroll
    for (int o = 1; o < 32; o <<= 1) {
        int v = __shfl_up_sync(~0u, inc, o);
        if (lane >= o) inc += v;
    }
    if (lane == 31) wsum[w] = inc;
    __syncthreads();
    if (w == 0) {
        int v = wsum[lane];
        int iv = v;
        #pragma unroll
        for (int o = 1; o < 32; o <<= 1) {
            int u = __shfl_up_sync(~0u, iv, o);
            if (lane >= o) iv += u;
        }
        wsum[lane] = iv - v;
    }
    __syncthreads();
    int run = wsum[w] + inc - s;
    for (int i = b; i < e; i++) {
        g_rowptr[i] = run;
        run += g_cnt[i];
    }
    if (t == 0) g_rowptr[N] = E2;
}

// ---- scatter edges into CSR: atomic-free ----
__global__ void k_scatter(const int* __restrict__ src, const int* __restrict__ dst,
                          const float* __restrict__ ea, int E, int N, float invE) {
    int e = blockIdx.x * blockDim.x + threadIdx.x;
    int E2 = E + N;
    if (e >= E2) return;
    int s, d; float av;
    if (e < E) { s = __ldg(&src[e]); d = __ldg(&dst[e]); av = __ldg(&ea[e]); }
    else       { s = d = e - E; av = g_easum * invE; }
    int2 rec; rec.x = s; rec.y = __float_as_int(av);
    g_edge[__ldg(&g_rowptr[d]) + g_pos[e]] = rec;
}

// ---- FUSED1: layer1 softmax+agg + relu + layer2 transform ----
__global__ void __launch_bounds__(256, 5)
k_fused1(const float* __restrict__ b1, const float* __restrict__ W2,
         const float* __restrict__ as2w, const float* __restrict__ ad2w,
         int N) {
    __shared__ __align__(16) float s_rec[WPB][32][8];
    int warp = (blockIdx.x * blockDim.x + threadIdx.x) >> 5;
    int lane = threadIdx.x & 31;
    int w = (threadIdx.x >> 5);
    if (warp >= N) return;
    int n = warp;
    int row = g_rowptr[n], end = g_rowptr[n + 1];

    float adh[NH], ceh[NH];
    #pragma unroll
    for (int h = 0; h < NH; h++) {
        adh[h] = __ldg(&g_ad1[n * NH + h]);
        ceh[h] = g_ce1[h];
    }
    int hA = lane >> 4;

    float ax0 = 0.f, ay0 = 0.f, ax1 = 0.f, ay1 = 0.f, ax2 = 0.f, ay2 = 0.f;
    float denh[NH] = {0.f, 0.f, 0.f, 0.f, 0.f};

    for (int base = row; base < end; base += 32) {
        int cnt = min(32, end - base);
        if (lane < cnt) {
            int2 r = g_edge[base + lane];
            int sA = r.x;
            float av = __int_as_float(r.y);
            float4 a4 = __ldg((const float4*)(g_as1 + sA * 8));
            float a5 = __ldg(&g_as1[sA * 8 + 4]);
            float lv[NH] = {a4.x, a4.y, a4.z, a4.w, a5};
            float ex[NH];
            #pragma unroll
            for (int h = 0; h < NH; h++) {
                float l = lv[h] + adh[h] + av * ceh[h];
                l = l > 0.f ? l : 0.2f * l;
                ex[h] = __expf(l);
                denh[h] += ex[h];
            }
            float2* rec = (float2*)s_rec[w][lane];
            float2 p0; p0.x = ex[0]; p0.y = ex[2];
            float2 p1; p1.x = ex[1]; p1.y = ex[3];
            float2 p2; p2.x = ex[4]; p2.y = __int_as_float(sA);
            rec[0] = p0; rec[1] = p1; rec[2] = p2;
        }
        __syncwarp();
        #pragma unroll 2
        for (int j = 0; j < cnt; j++) {
            float2 pab = *(const float2*)&s_rec[w][j][2 * hA];
            float2 p4s = *(const float2*)&s_rec[w][j][4];
            int s = __float_as_int(p4s.y);
            float a0 = pab.x, a1 = pab.y, a2 = p4s.x;
            const __half2* hb = (const __half2*)(g_h1h + (size_t)s * HCP);
            __half2 v0 = __ldg(&hb[lane]);
            __half2 v1 = __ldg(&hb[32 + lane]);
            float2 f0 = __half22float2(v0), f1 = __half22float2(v1);
            ax0 = fmaf(a0, f0.x, ax0); ay0 = fmaf(a0, f0.y, ay0);
            ax1 = fmaf(a1, f1.x, ax1); ay1 = fmaf(a1, f1.y, ay1);
            if (lane < 16) {
                __half2 v2 = __ldg(&hb[64 + lane]);
                float2 f2 = __half22float2(v2);
                ax2 = fmaf(a2, f2.x, ax2); ay2 = fmaf(a2, f2.y, ay2);
            }
        }
        __syncwarp();
    }

    #pragma unroll
    for (int h = 0; h < NH; h++) {
        #pragma unroll
        for (int o = 16; o; o >>= 1) denh[h] += __shfl_xor_sync(~0u, denh[h], o);
        denh[h] += 1e-16f;
    }
    float dA = denh[hA], dB = denh[2 + hA], dC = denh[4];

    float a2h[NH] = {0.f, 0.f, 0.f, 0.f, 0.f};
    int k; float v;
    #define DO_CH(val, dd, kk) \
        k = (kk); v = (val) / (dd) + __ldg(&b1[k]); v = fmaxf(v, 0.f); \
        _Pragma("unroll") \
        for (int h = 0; h < NH; h++) a2h[h] = fmaf(v, __ldg(&W2[k * NH + h]), a2h[h]);
    DO_CH(ax0, dA, 2 * lane)
    DO_CH(ay0, dA, 2 * lane + 1)
    DO_CH(ax1, dB, 64 + 2 * lane)
    DO_CH(ay1, dB, 65 + 2 * lane)
    if (lane < 16) {
        DO_CH(ax2, dC, 128 + 2 * lane)
        DO_CH(ay2, dC, 129 + 2 * lane)
    }
    #undef DO_CH
    #pragma unroll
    for (int h = 0; h < NH; h++)
        #pragma unroll
        for (int o = 16; o; o >>= 1) a2h[h] += __shfl_xor_sync(~0u, a2h[h], o);
    if (lane == 0) {
        __half2 q0 = __floats2half2_rn(a2h[0], a2h[1]);
        __half2 q1 = __floats2half2_rn(a2h[2], a2h[3]);
        __half2 q2 = __floats2half2_rn(a2h[4], 0.f);
        __half2 q3 = __floats2half2_rn(0.f, 0.f);
        int4 pk;
        pk.x = *(int*)&q0; pk.y = *(int*)&q1; pk.z = *(int*)&q2; pk.w = *(int*)&q3;
        *(int4*)(g_h2h + n * 8) = pk;
        #pragma unroll
        for (int h = 0; h < NH; h++)
            g_ad2[n * NH + h] = a2h[h] * __ldg(&ad2w[h]);
    }
}

// ---- FUSED2: layer2 softmax+agg + head-mean + Wlin + sigmoid ----
__global__ void k_fused2(const float* __restrict__ as2w,
                         const float* __restrict__ b2, const float* __restrict__ Wlin,
                         float* __restrict__ out, int N) {
    int warp = (blockIdx.x * blockDim.x + threadIdx.x) >> 5;
    int lane = threadIdx.x & 31;
    if (warp >= N) return;
    int n = warp;
    int row = g_rowptr[n], end = g_rowptr[n + 1];

    float adh[NH], ceh[NH], aw[NH];
    #pragma unroll
    for (int h = 0; h < NH; h++) {
        adh[h] = __ldg(&g_ad2[n * NH + h]);
        ceh[h] = g_ce2[h];
        aw[h]  = __ldg(&as2w[h]);
    }
    float acch[NH] = {0.f, 0.f, 0.f, 0.f, 0.f};
    float denh[NH] = {0.f, 0.f, 0.f, 0.f, 0.f};

    for (int base = row; base < end; base += 32) {
        int e = base + lane;
        if (e < end) {
            int2 r = g_edge[e];
            int s = r.x;
            float av = __int_as_float(r.y);
            int4 vp = __ldg((const int4*)(g_h2h + s * 8));
            float2 f01 = __half22float2(*(__half2*)&vp.x);
            float2 f23 = __half22float2(*(__half2*)&vp.y);
            float2 f45 = __half22float2(*(__half2*)&vp.z);
            float h2v[NH] = {f01.x, f01.y, f23.x, f23.y, f45.x};
            #pragma unroll
            for (int h = 0; h < NH; h++) {
                float l = fmaf(h2v[h], aw[h], adh[h] + av * ceh[h]);
                l = l > 0.f ? l : 0.2f * l;
                float ex = __expf(l);
                denh[h] += ex;
                acch[h] = fmaf(ex, h2v[h], acch[h]);
            }
        }
    }
    #pragma unroll
    for (int h = 0; h < NH; h++)
        #pragma unroll
        for (int o = 16; o; o >>= 1) {
            acch[h] += __shfl_xor_sync(~0u, acch[h], o);
            denh[h] += __shfl_xor_sync(~0u, denh[h], o);
        }
    if (lane == 0) {
        float ssum = 0.f;
        #pragma unroll
        for (int h = 0; h < NH; h++) ssum += acch[h] / (denh[h] + 1e-16f);
        float y = (ssum * (1.0f / NH) + __ldg(&b2[0])) * __ldg(&Wlin[0]);
        out[n] = 1.0f / (1.0f + expf(-y));
    }
}

extern "C" void kernel_launch(void* const* d_in, const int* in_sizes, int n_in,
                              void* d_out, int out_size) {
    const float* x      = (const float*)d_in[0];
    const float* ea     = (const float*)d_in[1];
    const int*   src    = (const int*)d_in[2];
    const int*   dst    = (const int*)d_in[3];
    const float* W1     = (const float*)d_in[4];
    const float* a_src1 = (const float*)d_in[5];
    const float* a_dst1 = (const float*)d_in[6];
    const float* We1    = (const float*)d_in[7];
    const float* ae1    = (const float*)d_in[8];
    const float* b1     = (const float*)d_in[9];
    const float* W2     = (const float*)d_in[10];
    const float* a_src2 = (const float*)d_in[11];
    const float* a_dst2 = (const float*)d_in[12];
    const float* We2    = (const float*)d_in[13];
    const float* ae2    = (const float*)d_in[14];
    const float* b2     = (const float*)d_in[15];
    const float* Wlin   = (const float*)d_in[16];

    int N  = in_sizes[0] / 5;
    int E  = in_sizes[2];
    int E2 = E + N;
    float invE = 1.0f / (float)E;

    int countBlocks = (E2 + 255) / 256;
    int nodeBlocks  = (N * 32 + 255) / 256;
    k_pre<<<(N + 255) / 256, 256>>>(We1, ae1, We2, ae2, W1, a_src1, a_dst1, N);
    k_combo<<<countBlocks + nodeBlocks, 256>>>(dst, ea, x, W1, E, N, countBlocks);
    k_scan<<<1, 1024>>>(N, E2);
    k_scatter<<<(E2 + 255) / 256, 256>>>(src, dst, ea, E, N, invE);
    k_fused1<<<(N * 32 + 255) / 256, 256>>>(b1, W2, a_src2, a_dst2, N);
    k_fused2<<<(N * 32 + 255) / 256, 256>>>(a_src2, b2, Wlin, (float*)d_out, N);
}

// round 12
// speedup vs baseline: 1.0965x; 1.0222x over previous
#include <cuda_runtime.h>
#include <cuda_fp16.h>

#define NMAX 50000
#define EMAX 800000
#define E2MAX (EMAX + NMAX)
#define HC 160
#define HCP 192   // padded h1 row: 384 B, 128B-aligned
#define NH 5
#define NC 32
#define WPB 8
#define POSB 14   // bits for position-within-row in packed g_pos

// ---- scratch (static device globals) ----
__device__ __align__(128) __half g_h1h[(size_t)NMAX * HCP];
__device__ __align__(16) float g_as1[NMAX * 8];     // as1 fp32, padded to 8
__device__ float g_ad1[NMAX * NH];
__device__ __align__(16) __half g_h2h[NMAX * 8];    // h2 (fp16), 16B/node
__device__ float g_ad2[NMAX * NH];
__device__ float g_ce1[NH], g_ce2[NH];
__device__ float g_wasad[5 * 16];
__device__ float g_easum;
__device__ __align__(16) int g_cnt[NMAX];
__device__ int   g_rowptr[NMAX + 1];
__device__ int   g_pos[E2MAX];                      // packed: (d << POSB) | pos
__device__ __align__(8) int2 g_edge[E2MAX];         // {src, ea-bits}

// ---- pre: zero counters + attention constant tables ----
__global__ void k_pre(const float* __restrict__ We1, const float* __restrict__ ae1,
                      const float* __restrict__ We2, const float* __restrict__ ae2,
                      const float* __restrict__ W1,
                      const float* __restrict__ a_src1, const float* __restrict__ a_dst1,
                      int N) {
    int i = blockIdx.x * blockDim.x + threadIdx.x;
    if (i < N) g_cnt[i] = 0;
    if (blockIdx.x == 0) {
        int t = threadIdx.x;
        if (t == 0) g_easum = 0.f;
        if (t < NH) {
            float s = 0.f;
            for (int c = 0; c < NC; c++) s += We1[t * NC + c] * ae1[t * NC + c];
            g_ce1[t] = s;
            g_ce2[t] = We2[t] * ae2[t];
        }
        if (t >= 64 && t < 114) {
            int u = t - 64;
            int f = u / 10, j = u % 10;
            int h = (j < 5) ? j : j - 5;
            const float* a = (j < 5) ? a_src1 : a_dst1;
            float s = 0.f;
            for (int c = 0; c < NC; c++) s += W1[f * HC + h * NC + c] * a[h * NC + c];
            g_wasad[f * 16 + j] = s;
        }
    }
}

// ---- combo: [count in-degree (save packed pos) + easum] || [node1 transform] ----
__global__ void k_combo(const int* __restrict__ dst, const float* __restrict__ ea,
                        const float* __restrict__ x, const float* __restrict__ W1,
                        int E, int N, int countBlocks) {
    if ((int)blockIdx.x < countBlocks) {
        int e = blockIdx.x * blockDim.x + threadIdx.x;
        int E2 = E + N;
        float s = 0.f;
        if (e < E2) {
            int d = (e < E) ? __ldg(&dst[e]) : (e - E);
            int pos = atomicAdd(&g_cnt[d], 1);
            g_pos[e] = (d << POSB) | pos;
            if (e < E) s = __ldg(&ea[e]);
        }
        #pragma unroll
        for (int o = 16; o; o >>= 1) s += __shfl_xor_sync(~0u, s, o);
        if ((threadIdx.x & 31) == 0 && s != 0.f) atomicAdd(&g_easum, s);
    } else {
        int warp = (((int)blockIdx.x - countBlocks) * blockDim.x + threadIdx.x) >> 5;
        int lane = threadIdx.x & 31;
        if (warp >= N) return;
        int n = warp;
        float xf[5];
        #pragma unroll
        for (int f = 0; f < 5; f++) xf[f] = __ldg(&x[n * 5 + f]);
        #pragma unroll
        for (int h = 0; h < NH; h++) {
            int col = h * NC + lane;
            float acc = 0.f;
            #pragma unroll
            for (int f = 0; f < 5; f++) acc = fmaf(xf[f], __ldg(&W1[f * HC + col]), acc);
            g_h1h[(size_t)n * HCP + col] = __float2half(acc);
        }
        if (lane < 10) {
            float acc = 0.f;
            #pragma unroll
            for (int f = 0; f < 5; f++) acc = fmaf(xf[f], g_wasad[f * 16 + lane], acc);
            if (lane < 5) g_as1[n * 8 + lane] = acc;
            else          g_ad1[n * NH + (lane - 5)] = acc;
        }
    }
}

// ---- single-block exclusive scan (int4-vectorized partial sums) ----
__global__ void k_scan(int N, int E2) {
    __shared__ int wsum[32];
    int t = threadIdx.x;
    int lane = t & 31, w = t >> 5;
    int chunk = ((N + 1023) / 1024 + 3) & ~3;   // multiple of 4
    int b = t * chunk, e = min(b + chunk, N);
    int s = 0;
    int i = b;
    for (; i + 3 < e; i += 4) {
        int4 v = *(const int4*)(g_cnt + i);
        s += v.x + v.y + v.z + v.w;
    }
    for (; i < e; i++) s += g_cnt[i];
    int inc = s;
    #pragma unroll
    for (int o = 1; o < 32; o <<= 1) {
        int v = __shfl_up_sync(~0u, inc, o);
        if (lane >= o) inc += v;
    }
    if (lane == 31) wsum[w] = inc;
    __syncthreads();
    if (w == 0) {
        int v = wsum[lane];
        int iv = v;
        #pragma unroll
        for (int o = 1; o < 32; o <<= 1) {
            int u = __shfl_up_sync(~0u, iv, o);
            if (lane >= o) iv += u;
        }
        wsum[lane] = iv - v;
    }
    __syncthreads();
    int run = wsum[w] + inc - s;
    for (int j = b; j < e; j++) {
        g_rowptr[j] = run;
        run += g_cnt[j];
    }
    if (t == 0) g_rowptr[N] = E2;
}

// ---- scatter edges into CSR: atomic-free, packed pos ----
__global__ void k_scatter(const int* __restrict__ src,
                          const float* __restrict__ ea, int E, int N, float invE) {
    int e = blockIdx.x * blockDim.x + threadIdx.x;
    int E2 = E + N;
    if (e >= E2) return;
    int pk = g_pos[e];
    int d = pk >> POSB;
    int pos = pk & ((1 << POSB) - 1);
    int s; float av;
    if (e < E) { s = __ldg(&src[e]); av = __ldg(&ea[e]); }
    else       { s = e - E; av = g_easum * invE; }
    int2 rec; rec.x = s; rec.y = __float_as_int(av);
    g_edge[__ldg(&g_rowptr[d]) + pos] = rec;
}

// ---- FUSED1: layer1 softmax+agg + relu + layer2 transform ----
__global__ void __launch_bounds__(256, 6)
k_fused1(const float* __restrict__ b1, const float* __restrict__ W2,
         const float* __restrict__ as2w, const float* __restrict__ ad2w,
         int N) {
    __shared__ __align__(16) float s_rec[WPB][32][8];
    int warp = (blockIdx.x * blockDim.x + threadIdx.x) >> 5;
    int lane = threadIdx.x & 31;
    int w = (threadIdx.x >> 5);
    if (warp >= N) return;
    int n = warp;
    int row = g_rowptr[n], end = g_rowptr[n + 1];

    float adh[NH], ceh[NH];
    #pragma unroll
    for (int h = 0; h < NH; h++) {
        adh[h] = __ldg(&g_ad1[n * NH + h]);
        ceh[h] = g_ce1[h];
    }
    int hA = lane >> 4;

    float ax0 = 0.f, ay0 = 0.f, ax1 = 0.f, ay1 = 0.f, ax2 = 0.f, ay2 = 0.f;
    float denh[NH] = {0.f, 0.f, 0.f, 0.f, 0.f};

    for (int base = row; base < end; base += 32) {
        int cnt = min(32, end - base);
        if (lane < cnt) {
            int2 r = g_edge[base + lane];
            int sA = r.x;
            float av = __int_as_float(r.y);
            float4 a4 = __ldg((const float4*)(g_as1 + sA * 8));
            float a5 = __ldg(&g_as1[sA * 8 + 4]);
            float lv[NH] = {a4.x, a4.y, a4.z, a4.w, a5};
            float ex[NH];
            #pragma unroll
            for (int h = 0; h < NH; h++) {
                float l = lv[h] + adh[h] + av * ceh[h];
                l = l > 0.f ? l : 0.2f * l;
                ex[h] = __expf(l);
                denh[h] += ex[h];
            }
            float2* rec = (float2*)s_rec[w][lane];
            float2 p0; p0.x = ex[0]; p0.y = ex[2];
            float2 p1; p1.x = ex[1]; p1.y = ex[3];
            float2 p2; p2.x = ex[4]; p2.y = __int_as_float(sA);
            rec[0] = p0; rec[1] = p1; rec[2] = p2;
        }
        __syncwarp();
        #pragma unroll 2
        for (int j = 0; j < cnt; j++) {
            float2 pab = *(const float2*)&s_rec[w][j][2 * hA];
            float2 p4s = *(const float2*)&s_rec[w][j][4];
            int s = __float_as_int(p4s.y);
            float a0 = pab.x, a1 = pab.y, a2 = p4s.x;
            const __half2* hb = (const __half2*)(g_h1h + (size_t)s * HCP);
            __half2 v0 = __ldg(&hb[lane]);
            __half2 v1 = __ldg(&hb[32 + lane]);
            float2 f0 = __half22float2(v0), f1 = __half22float2(v1);
            ax0 = fmaf(a0, f0.x, ax0); ay0 = fmaf(a0, f0.y, ay0);
            ax1 = fmaf(a1, f1.x, ax1); ay1 = fmaf(a1, f1.y, ay1);
            if (lane < 16) {
                __half2 v2 = __ldg(&hb[64 + lane]);
                float2 f2 = __half22float2(v2);
                ax2 = fmaf(a2, f2.x, ax2); ay2 = fmaf(a2, f2.y, ay2);
            }
        }
        __syncwarp();
    }

    #pragma unroll
    for (int h = 0; h < NH; h++) {
        #pragma unroll
        for (int o = 16; o; o >>= 1) denh[h] += __shfl_xor_sync(~0u, denh[h], o);
        denh[h] += 1e-16f;
    }
    float dA = denh[hA], dB = denh[2 + hA], dC = denh[4];

    float a2h[NH] = {0.f, 0.f, 0.f, 0.f, 0.f};
    int k; float v;
    #define DO_CH(val, dd, kk) \
        k = (kk); v = (val) / (dd) + __ldg(&b1[k]); v = fmaxf(v, 0.f); \
        _Pragma("unroll") \
        for (int h = 0; h < NH; h++) a2h[h] = fmaf(v, __ldg(&W2[k * NH + h]), a2h[h]);
    DO_CH(ax0, dA, 2 * lane)
    DO_CH(ay0, dA, 2 * lane + 1)
    DO_CH(ax1, dB, 64 + 2 * lane)
    DO_CH(ay1, dB, 65 + 2 * lane)
    if (lane < 16) {
        DO_CH(ax2, dC, 128 + 2 * lane)
        DO_CH(ay2, dC, 129 + 2 * lane)
    }
    #undef DO_CH
    #pragma unroll
    for (int h = 0; h < NH; h++)
        #pragma unroll
        for (int o = 16; o; o >>= 1) a2h[h] += __shfl_xor_sync(~0u, a2h[h], o);
    if (lane == 0) {
        __half2 q0 = __floats2half2_rn(a2h[0], a2h[1]);
        __half2 q1 = __floats2half2_rn(a2h[2], a2h[3]);
        __half2 q2 = __floats2half2_rn(a2h[4], 0.f);
        __half2 q3 = __floats2half2_rn(0.f, 0.f);
        int4 pk;
        pk.x = *(int*)&q0; pk.y = *(int*)&q1; pk.z = *(int*)&q2; pk.w = *(int*)&q3;
        *(int4*)(g_h2h + n * 8) = pk;
        #pragma unroll
        for (int h = 0; h < NH; h++)
            g_ad2[n * NH + h] = a2h[h] * __ldg(&ad2w[h]);
    }
}

// ---- FUSED2: layer2 softmax+agg + head-mean + Wlin + sigmoid ----
__global__ void k_fused2(const float* __restrict__ as2w,
                         const float* __restrict__ b2, const float* __restrict__ Wlin,
                         float* __restrict__ out, int N) {
    int warp = (blockIdx.x * blockDim.x + threadIdx.x) >> 5;
    int lane = threadIdx.x & 31;
    if (warp >= N) return;
    int n = warp;
    int row = g_rowptr[n], end = g_rowptr[n + 1];

    float adh[NH], ceh[NH], aw[NH];
    #pragma unroll
    for (int h = 0; h < NH; h++) {
        adh[h] = __ldg(&g_ad2[n * NH + h]);
        ceh[h] = g_ce2[h];
        aw[h]  = __ldg(&as2w[h]);
    }
    float acch[NH] = {0.f, 0.f, 0.f, 0.f, 0.f};
    float denh[NH] = {0.f, 0.f, 0.f, 0.f, 0.f};

    for (int base = row; base < end; base += 32) {
        int e = base + lane;
        if (e < end) {
            int2 r = g_edge[e];
            int s = r.x;
            float av = __int_as_float(r.y);
            int4 vp = __ldg((const int4*)(g_h2h + s * 8));
            float2 f01 = __half22float2(*(__half2*)&vp.x);
            float2 f23 = __half22float2(*(__half2*)&vp.y);
            float2 f45 = __half22float2(*(__half2*)&vp.z);
            float h2v[NH] = {f01.x, f01.y, f23.x, f23.y, f45.x};
            #pragma unroll
            for (int h = 0; h < NH; h++) {
                float l = fmaf(h2v[h], aw[h], adh[h] + av * ceh[h]);
                l = l > 0.f ? l : 0.2f * l;
                float ex = __expf(l);
                denh[h] += ex;
                acch[h] = fmaf(ex, h2v[h], acch[h]);
            }
        }
    }
    #pragma unroll
    for (int h = 0; h < NH; h++)
        #pragma unroll
        for (int o = 16; o; o >>= 1) {
            acch[h] += __shfl_xor_sync(~0u, acch[h], o);
            denh[h] += __shfl_xor_sync(~0u, denh[h], o);
        }
    if (lane == 0) {
        float ssum = 0.f;
        #pragma unroll
        for (int h = 0; h < NH; h++) ssum += acch[h] / (denh[h] + 1e-16f);
        float y = (ssum * (1.0f / NH) + __ldg(&b2[0])) * __ldg(&Wlin[0]);
        out[n] = 1.0f / (1.0f + expf(-y));
    }
}

extern "C" void kernel_launch(void* const* d_in, const int* in_sizes, int n_in,
                              void* d_out, int out_size) {
    const float* x      = (const float*)d_in[0];
    const float* ea     = (const float*)d_in[1];
    const int*   src    = (const int*)d_in[2];
    const int*   dst    = (const int*)d_in[3];
    const float* W1     = (const float*)d_in[4];
    const float* a_src1 = (const float*)d_in[5];
    const float* a_dst1 = (const float*)d_in[6];
    const float* We1    = (const float*)d_in[7];
    const float* ae1    = (const float*)d_in[8];
    const float* b1     = (const float*)d_in[9];
    const float* W2     = (const float*)d_in[10];
    const float* a_src2 = (const float*)d_in[11];
    const float* a_dst2 = (const float*)d_in[12];
    const float* We2    = (const float*)d_in[13];
    const float* ae2    = (const float*)d_in[14];
    const float* b2     = (const float*)d_in[15];
    const float* Wlin   = (const float*)d_in[16];

    int N  = in_sizes[0] / 5;
    int E  = in_sizes[2];
    int E2 = E + N;
    float invE = 1.0f / (float)E;

    int countBlocks = (E2 + 255) / 256;
    int nodeBlocks  = (N * 32 + 255) / 256;
    k_pre<<<(N + 255) / 256, 256>>>(We1, ae1, We2, ae2, W1, a_src1, a_dst1, N);
    k_combo<<<countBlocks + nodeBlocks, 256>>>(dst, ea, x, W1, E, N, countBlocks);
    k_scan<<<1, 1024>>>(N, E2);
    k_scatter<<<(E2 + 255) / 256, 256>>>(src, ea, E, N, invE);
    k_fused1<<<(N * 32 + 255) / 256, 256>>>(b1, W2, a_src2, a_dst2, N);
    k_fused2<<<(N * 32 + 255) / 256, 256>>>(a_src2, b2, Wlin, (float*)d_out, N);
}

// round 13
// speedup vs baseline: 1.2844x; 1.1714x over previous
#include <cuda_runtime.h>
#include <cuda_fp16.h>

#define NMAX 50000
#define EMAX 800000
#define E2MAX (EMAX + NMAX)
#define HC 160
#define NH 5
#define NC 32
#define WPB 8
#define POSB 14

// ---- scratch (static device globals) ----
__device__ __align__(16) float g_nA[NMAX * 16];     // per node: [as1[5] | x[5] | pad] (64B row)
__device__ float g_ad1[NMAX * NH];
__device__ __align__(16) __half g_h2h[NMAX * 8];    // h2 (fp16), 16B/node
__device__ float g_ad2[NMAX * NH];
__device__ float g_ce1[NH], g_ce2[NH];
__device__ float g_wasad[5 * 16];
__device__ float g_easum;
__device__ __align__(16) int g_cnt[NMAX];
__device__ int   g_rowptr[NMAX + 1];
__device__ int   g_pos[E2MAX];                      // packed: (d << POSB) | pos
__device__ __align__(8) int2 g_edge[E2MAX];         // {src, ea-bits}

// ---- pre: zero counters + attention constant tables ----
__global__ void k_pre(const float* __restrict__ We1, const float* __restrict__ ae1,
                      const float* __restrict__ We2, const float* __restrict__ ae2,
                      const float* __restrict__ W1,
                      const float* __restrict__ a_src1, const float* __restrict__ a_dst1,
                      int N) {
    int i = blockIdx.x * blockDim.x + threadIdx.x;
    if (i < N) g_cnt[i] = 0;
    if (blockIdx.x == 0) {
        int t = threadIdx.x;
        if (t == 0) g_easum = 0.f;
        if (t < NH) {
            float s = 0.f;
            for (int c = 0; c < NC; c++) s += We1[t * NC + c] * ae1[t * NC + c];
            g_ce1[t] = s;
            g_ce2[t] = We2[t] * ae2[t];
        }
        if (t >= 64 && t < 114) {
            int u = t - 64;
            int f = u / 10, j = u % 10;
            int h = (j < 5) ? j : j - 5;
            const float* a = (j < 5) ? a_src1 : a_dst1;
            float s = 0.f;
            for (int c = 0; c < NC; c++) s += W1[f * HC + h * NC + c] * a[h * NC + c];
            g_wasad[f * 16 + j] = s;
        }
    }
}

// ---- combo: [count in-degree + easum] || [node records: as1/ad1/x] ----
__global__ void k_combo(const int* __restrict__ dst, const float* __restrict__ ea,
                        const float* __restrict__ x,
                        int E, int N, int countBlocks) {
    if ((int)blockIdx.x < countBlocks) {
        int e = blockIdx.x * blockDim.x + threadIdx.x;
        int E2 = E + N;
        float s = 0.f;
        if (e < E2) {
            int d = (e < E) ? __ldg(&dst[e]) : (e - E);
            int pos = atomicAdd(&g_cnt[d], 1);
            g_pos[e] = (d << POSB) | pos;
            if (e < E) s = __ldg(&ea[e]);
        }
        #pragma unroll
        for (int o = 16; o; o >>= 1) s += __shfl_xor_sync(~0u, s, o);
        if ((threadIdx.x & 31) == 0 && s != 0.f) atomicAdd(&g_easum, s);
    } else {
        __shared__ float sw[80];
        if (threadIdx.x < 80) sw[threadIdx.x] = g_wasad[threadIdx.x];
        __syncthreads();
        int n = ((int)blockIdx.x - countBlocks) * blockDim.x + threadIdx.x;
        if (n >= N) return;
        float xf[5];
        #pragma unroll
        for (int f = 0; f < 5; f++) xf[f] = __ldg(&x[n * 5 + f]);
        float as[NH], ad[NH];
        #pragma unroll
        for (int h = 0; h < NH; h++) {
            float a = 0.f, b = 0.f;
            #pragma unroll
            for (int f = 0; f < 5; f++) {
                a = fmaf(xf[f], sw[f * 16 + h], a);
                b = fmaf(xf[f], sw[f * 16 + 5 + h], b);
            }
            as[h] = a; ad[h] = b;
        }
        float4* rowp = (float4*)(g_nA + n * 16);
        float4 r0; r0.x = as[0]; r0.y = as[1]; r0.z = as[2]; r0.w = as[3];
        float4 r1; r1.x = as[4]; r1.y = xf[0]; r1.z = xf[1]; r1.w = xf[2];
        float4 r2; r2.x = xf[3]; r2.y = xf[4]; r2.z = 0.f; r2.w = 0.f;
        rowp[0] = r0; rowp[1] = r1; rowp[2] = r2;
        #pragma unroll
        for (int h = 0; h < NH; h++) g_ad1[n * NH + h] = ad[h];
    }
}

// ---- single-block exclusive scan (int4-vectorized partial sums) ----
__global__ void k_scan(int N, int E2) {
    __shared__ int wsum[32];
    int t = threadIdx.x;
    int lane = t & 31, w = t >> 5;
    int chunk = ((N + 1023) / 1024 + 3) & ~3;
    int b = t * chunk, e = min(b + chunk, N);
    int s = 0;
    int i = b;
    for (; i + 3 < e; i += 4) {
        int4 v = *(const int4*)(g_cnt + i);
        s += v.x + v.y + v.z + v.w;
    }
    for (; i < e; i++) s += g_cnt[i];
    int inc = s;
    #pragma unroll
    for (int o = 1; o < 32; o <<= 1) {
        int v = __shfl_up_sync(~0u, inc, o);
        if (lane >= o) inc += v;
    }
    if (lane == 31) wsum[w] = inc;
    __syncthreads();
    if (w == 0) {
        int v = wsum[lane];
        int iv = v;
        #pragma unroll
        for (int o = 1; o < 32; o <<= 1) {
            int u = __shfl_up_sync(~0u, iv, o);
            if (lane >= o) iv += u;
        }
        wsum[lane] = iv - v;
    }
    __syncthreads();
    int run = wsum[w] + inc - s;
    for (int j = b; j < e; j++) {
        g_rowptr[j] = run;
        run += g_cnt[j];
    }
    if (t == 0) g_rowptr[N] = E2;
}

// ---- scatter edges into CSR: atomic-free, packed pos ----
__global__ void k_scatter(const int* __restrict__ src,
                          const float* __restrict__ ea, int E, int N, float invE) {
    int e = blockIdx.x * blockDim.x + threadIdx.x;
    int E2 = E + N;
    if (e >= E2) return;
    int pk = g_pos[e];
    int d = pk >> POSB;
    int pos = pk & ((1 << POSB) - 1);
    int s; float av;
    if (e < E) { s = __ldg(&src[e]); av = __ldg(&ea[e]); }
    else       { s = e - E; av = g_easum * invE; }
    int2 rec; rec.x = s; rec.y = __float_as_int(av);
    g_edge[__ldg(&g_rowptr[d]) + pos] = rec;
}

// ---- FUSED1: layer1 softmax+agg (factored via S = sum ex*x) + relu + layer2 ----
// warp per dst node.
// phase A (lane-per-edge): gather [as1|x] row, compute ex[5], stage {ex[5],x[5],1}.
// phase B: 30 lanes accumulate S[h,f] (lane=h*5+f) / den[h] (lane=25+h), 1 reg each.
// epilogue: msg[k] = sum_f S[h,f] W1[f,k]; relu(+b1) -> W2 GEMV.
__global__ void __launch_bounds__(256, 6)
k_fused1(const float* __restrict__ b1, const float* __restrict__ W1,
         const float* __restrict__ W2,
         const float* __restrict__ as2w, const float* __restrict__ ad2w,
         int N) {
    __shared__ __align__(16) float s_rec[WPB][32][12];
    __shared__ float s_S[WPB][32];
    int warp = (blockIdx.x * blockDim.x + threadIdx.x) >> 5;
    int lane = threadIdx.x & 31;
    int w = (threadIdx.x >> 5);
    if (warp >= N) return;
    int n = warp;
    int row = g_rowptr[n], end = g_rowptr[n + 1];

    float adh[NH], ceh[NH];
    #pragma unroll
    for (int h = 0; h < NH; h++) {
        adh[h] = __ldg(&g_ad1[n * NH + h]);
        ceh[h] = g_ce1[h];
    }

    // phase-B role of this lane
    int myh = (lane < 25) ? (lane / 5) : (lane - 25);
    int myf = (lane < 25) ? (lane % 5) : 5;          // f=5 reads the staged 1.0
    float Sacc = 0.f;

    for (int base = row; base < end; base += 32) {
        int cnt = min(32, end - base);
        // --- phase A ---
        if (lane < cnt) {
            int2 r = g_edge[base + lane];
            int sA = r.x;
            float av = __int_as_float(r.y);
            const float4* rowp = (const float4*)(g_nA + sA * 16);
            float4 A = __ldg(rowp);
            float4 B = __ldg(rowp + 1);
            float4 C = __ldg(rowp + 2);
            float asv[NH] = {A.x, A.y, A.z, A.w, B.x};
            float ex[NH];
            #pragma unroll
            for (int h = 0; h < NH; h++) {
                float l = asv[h] + adh[h] + av * ceh[h];
                l = l > 0.f ? l : 0.2f * l;
                ex[h] = __expf(l);
            }
            float4* rec = (float4*)s_rec[w][lane];
            float4 p0; p0.x = ex[0]; p0.y = ex[1]; p0.z = ex[2]; p0.w = ex[3];
            float4 p1; p1.x = ex[4]; p1.y = B.y; p1.z = B.z; p1.w = B.w;  // ex4, x0..2
            float4 p2; p2.x = C.x; p2.y = C.y; p2.z = 1.0f; p2.w = 0.f;   // x3,x4,1,pad
            rec[0] = p0; rec[1] = p1; rec[2] = p2;
        }
        __syncwarp();
        // --- phase B: one accumulator per lane ---
        if (lane < 30) {
            int j = 0;
            #pragma unroll 2
            for (; j < cnt; j++)
                Sacc = fmaf(s_rec[w][j][myh], s_rec[w][j][5 + myf], Sacc);
        }
        __syncwarp();
    }

    if (lane < 30) s_S[w][lane] = Sacc;
    __syncwarp();

    // epilogue: every lane owns channels k = i*32+lane (head i)
    float dinv[NH];
    #pragma unroll
    for (int h = 0; h < NH; h++) dinv[h] = 1.0f / (s_S[w][25 + h] + 1e-16f);

    float a2h[NH] = {0.f, 0.f, 0.f, 0.f, 0.f};
    #pragma unroll
    for (int i = 0; i < 5; i++) {
        int k = i * NC + lane;
        float msg = 0.f;
        #pragma unroll
        for (int f = 0; f < 5; f++)
            msg = fmaf(s_S[w][i * 5 + f], __ldg(&W1[f * HC + k]), msg);
        float v = msg * dinv[i] + __ldg(&b1[k]);
        v = fmaxf(v, 0.f);
        #pragma unroll
        for (int h = 0; h < NH; h++)
            a2h[h] = fmaf(v, __ldg(&W2[k * NH + h]), a2h[h]);
    }
    #pragma unroll
    for (int h = 0; h < NH; h++)
        #pragma unroll
        for (int o = 16; o; o >>= 1) a2h[h] += __shfl_xor_sync(~0u, a2h[h], o);
    if (lane == 0) {
        __half2 q0 = __floats2half2_rn(a2h[0], a2h[1]);
        __half2 q1 = __floats2half2_rn(a2h[2], a2h[3]);
        __half2 q2 = __floats2half2_rn(a2h[4], 0.f);
        __half2 q3 = __floats2half2_rn(0.f, 0.f);
        int4 pk;
        pk.x = *(int*)&q0; pk.y = *(int*)&q1; pk.z = *(int*)&q2; pk.w = *(int*)&q3;
        *(int4*)(g_h2h + n * 8) = pk;
        #pragma unroll
        for (int h = 0; h < NH; h++)
            g_ad2[n * NH + h] = a2h[h] * __ldg(&ad2w[h]);
    }
}

// ---- FUSED2: layer2 softmax+agg + head-mean + Wlin + sigmoid ----
__global__ void k_fused2(const float* __restrict__ as2w,
                         const float* __restrict__ b2, const float* __restrict__ Wlin,
                         float* __restrict__ out, int N) {
    int warp = (blockIdx.x * blockDim.x + threadIdx.x) >> 5;
    int lane = threadIdx.x & 31;
    if (warp >= N) return;
    int n = warp;
    int row = g_rowptr[n], end = g_rowptr[n + 1];

    float adh[NH], ceh[NH], aw[NH];
    #pragma unroll
    for (int h = 0; h < NH; h++) {
        adh[h] = __ldg(&g_ad2[n * NH + h]);
        ceh[h] = g_ce2[h];
        aw[h]  = __ldg(&as2w[h]);
    }
    float acch[NH] = {0.f, 0.f, 0.f, 0.f, 0.f};
    float denh[NH] = {0.f, 0.f, 0.f, 0.f, 0.f};

    for (int base = row; base < end; base += 32) {
        int e = base + lane;
        if (e < end) {
            int2 r = g_edge[e];
            int s = r.x;
            float av = __int_as_float(r.y);
            int4 vp = __ldg((const int4*)(g_h2h + s * 8));
            float2 f01 = __half22float2(*(__half2*)&vp.x);
            float2 f23 = __half22float2(*(__half2*)&vp.y);
            float2 f45 = __half22float2(*(__half2*)&vp.z);
            float h2v[NH] = {f01.x, f01.y, f23.x, f23.y, f45.x};
            #pragma unroll
            for (int h = 0; h < NH; h++) {
                float l = fmaf(h2v[h], aw[h], adh[h] + av * ceh[h]);
                l = l > 0.f ? l : 0.2f * l;
                float ex = __expf(l);
                denh[h] += ex;
                acch[h] = fmaf(ex, h2v[h], acch[h]);
            }
        }
    }
    #pragma unroll
    for (int h = 0; h < NH; h++)
        #pragma unroll
        for (int o = 16; o; o >>= 1) {
            acch[h] += __shfl_xor_sync(~0u, acch[h], o);
            denh[h] += __shfl_xor_sync(~0u, denh[h], o);
        }
    if (lane == 0) {
        float ssum = 0.f;
        #pragma unroll
        for (int h = 0; h < NH; h++) ssum += acch[h] / (denh[h] + 1e-16f);
        float y = (ssum * (1.0f / NH) + __ldg(&b2[0])) * __ldg(&Wlin[0]);
        out[n] = 1.0f / (1.0f + expf(-y));
    }
}

extern "C" void kernel_launch(void* const* d_in, const int* in_sizes, int n_in,
                              void* d_out, int out_size) {
    const float* x      = (const float*)d_in[0];
    const float* ea     = (const float*)d_in[1];
    const int*   src    = (const int*)d_in[2];
    const int*   dst    = (const int*)d_in[3];
    const float* W1     = (const float*)d_in[4];
    const float* a_src1 = (const float*)d_in[5];
    const float* a_dst1 = (const float*)d_in[6];
    const float* We1    = (const float*)d_in[7];
    const float* ae1    = (const float*)d_in[8];
    const float* b1     = (const float*)d_in[9];
    const float* W2     = (const float*)d_in[10];
    const float* a_src2 = (const float*)d_in[11];
    const float* a_dst2 = (const float*)d_in[12];
    const float* We2    = (const float*)d_in[13];
    const float* ae2    = (const float*)d_in[14];
    const float* b2     = (const float*)d_in[15];
    const float* Wlin   = (const float*)d_in[16];

    int N  = in_sizes[0] / 5;
    int E  = in_sizes[2];
    int E2 = E + N;
    float invE = 1.0f / (float)E;

    int countBlocks = (E2 + 255) / 256;
    int nodeBlocks  = (N + 255) / 256;
    k_pre<<<(N + 255) / 256, 256>>>(We1, ae1, We2, ae2, W1, a_src1, a_dst1, N);
    k_combo<<<countBlocks + nodeBlocks, 256>>>(dst, ea, x, E, N, countBlocks);
    k_scan<<<1, 1024>>>(N, E2);
    k_scatter<<<(E2 + 255) / 256, 256>>>(src, ea, E, N, invE);
    k_fused1<<<(N * 32 + 255) / 256, 256>>>(b1, W1, W2, a_src2, a_dst2, N);
    k_fused2<<<(N * 32 + 255) / 256, 256>>>(a_src2, b2, Wlin, (float*)d_out, N);
}